// round 12
// baseline (speedup 1.0000x reference)
#include <cuda_runtime.h>
#include <math.h>

#define THW 65536
#define C_ 32
#define KNN 8

// Scratch (allowed: __device__ globals, no allocation)
__device__ float g_stacked[256 * THW];   // 64 MB: [k*C+c][THW]
__device__ float g_x[C_ * THW];          // 8 MB : conv output [C][THW]
__device__ float g_wT[9 * 256 * 32];     // tf32-rounded conv weights [tap][ic][o]

__device__ __forceinline__ float tf32_rna(float v) {
    unsigned u;
    asm("cvt.rna.tf32.f32 %0, %1;" : "=r"(u) : "f"(v));
    return __uint_as_float(u);
}

// ---------------------------------------------------------------------------
// Stage 1: non-local kNN search. ONE thread owns TWO h-adjacent voxels
// (t,h,w) and (t,h+1,w); neighbor loads for shared rows feed both distance
// chains (LDG per voxel: 7776 -> 4320). Iteration dt asc -> hr asc -> dw asc
// preserves meshgrid order for each voxel (A skips hr=h+5, B skips hr=h-4).
// ---------------------------------------------------------------------------
__global__ __launch_bounds__(128) void nl_stack_kernel(const float* __restrict__ vid) {
    int gtid = blockIdx.x * 128 + threadIdx.x;   // 32768 threads
    int w  = gtid & 127;                          // lanes vary w -> coalesced
    int h2 = (gtid >> 7) & 63;
    int t  = gtid >> 13;
    int h  = h2 * 2;
    int pA = t * 16384 + h * 128 + w;
    int pB = pA + 128;

    float xA[C_], xB[C_];
#pragma unroll
    for (int c = 0; c < C_; c++) {
        xA[c] = vid[c * THW + pA];
        xB[c] = vid[c * THW + pB];
    }

    float bdA[KNN], bdB[KNN];
    int   bqA[KNN], bqB[KNN];
#pragma unroll
    for (int k = 0; k < KNN; k++) {
        bdA[k] = 3.4e38f; bqA[k] = 0;
        bdB[k] = 3.4e38f; bqB[k] = 0;
    }

    for (int dt = -1; dt <= 1; dt++) {
        int ti = t + dt; ti = ti < 0 ? 0 : (ti > 3 ? 3 : ti);
        int tbase = ti * 16384;
        for (int hr = h - 4; hr <= h + 5; hr++) {
            int hc = hr < 0 ? 0 : (hr > 127 ? 127 : hr);
            int rowbase = tbase + hc * 128;
            bool useA = (hr - h) <= 4;    // A's dh in [-4,4]
            bool useB = (hr - h) >= -3;   // B's dh in [-4,4]
            for (int dw = -4; dw <= 4; dw++) {
                int wi = w + dw; wi = wi < 0 ? 0 : (wi > 127 ? 127 : wi);
                int q = rowbase + wi;
                // 4-wide partial chains per voxel (matches prior summation order)
                float a0 = 0, a1 = 0, a2 = 0, a3 = 0;
                float b0 = 0, b1 = 0, b2 = 0, b3 = 0;
#pragma unroll
                for (int c = 0; c < C_; c += 4) {
                    float n0 = vid[(c + 0) * THW + q];
                    float n1 = vid[(c + 1) * THW + q];
                    float n2 = vid[(c + 2) * THW + q];
                    float n3 = vid[(c + 3) * THW + q];
                    float dA0 = xA[c + 0] - n0, dB0 = xB[c + 0] - n0;
                    float dA1 = xA[c + 1] - n1, dB1 = xB[c + 1] - n1;
                    float dA2 = xA[c + 2] - n2, dB2 = xB[c + 2] - n2;
                    float dA3 = xA[c + 3] - n3, dB3 = xB[c + 3] - n3;
                    a0 = fmaf(dA0, dA0, a0); b0 = fmaf(dB0, dB0, b0);
                    a1 = fmaf(dA1, dA1, a1); b1 = fmaf(dB1, dB1, b1);
                    a2 = fmaf(dA2, dA2, a2); b2 = fmaf(dB2, dB2, b2);
                    a3 = fmaf(dA3, dA3, a3); b3 = fmaf(dB3, dB3, b3);
                }
                float dA = (a0 + a1) + (a2 + a3);
                float dB = (b0 + b1) + (b2 + b3);
                if (useA && dA < bdA[KNN - 1]) {
                    int ins = KNN - 1;
#pragma unroll
                    for (int k = KNN - 2; k >= 0; k--) {
                        if (dA < bdA[k]) { bdA[k + 1] = bdA[k]; bqA[k + 1] = bqA[k]; ins = k; }
                    }
                    bdA[ins] = dA; bqA[ins] = q;
                }
                if (useB && dB < bdB[KNN - 1]) {
                    int ins = KNN - 1;
#pragma unroll
                    for (int k = KNN - 2; k >= 0; k--) {
                        if (dB < bdB[k]) { bdB[k + 1] = bdB[k]; bqB[k + 1] = bqB[k]; ins = k; }
                    }
                    bdB[ins] = dB; bqB[ins] = q;
                }
            }
        }
    }

    // softmax(-d) + weighted gather-stack, voxel A
    {
        float e[KNN], s = 0.0f;
#pragma unroll
        for (int k = 0; k < KNN; k++) { e[k] = __expf(bdA[0] - bdA[k]); s += e[k]; }
        float inv = 1.0f / s;
#pragma unroll
        for (int k = 0; k < KNN; k++) {
            float wk = e[k] * inv;
            int q = bqA[k];
#pragma unroll
            for (int c = 0; c < C_; c++) {
                g_stacked[(k * C_ + c) * THW + pA] = vid[c * THW + q] * wk;
            }
        }
    }
    // voxel B
    {
        float e[KNN], s = 0.0f;
#pragma unroll
        for (int k = 0; k < KNN; k++) { e[k] = __expf(bdB[0] - bdB[k]); s += e[k]; }
        float inv = 1.0f / s;
#pragma unroll
        for (int k = 0; k < KNN; k++) {
            float wk = e[k] * inv;
            int q = bqB[k];
#pragma unroll
            for (int c = 0; c < C_; c++) {
                g_stacked[(k * C_ + c) * THW + pB] = vid[c * THW + q] * wk;
            }
        }
    }
}

// ---------------------------------------------------------------------------
// Weight pre-transform (unchanged)
// ---------------------------------------------------------------------------
__global__ __launch_bounds__(128) void wT_kernel(const float* __restrict__ cw) {
    int i = blockIdx.x * 128 + threadIdx.x;
    int o = i & 31;
    int ic = (i >> 5) & 255;
    int tap = i >> 13;
    g_wT[i] = tf32_rna(cw[(o * 256 + ic) * 9 + tap]);
}

// ---------------------------------------------------------------------------
// Stage 2: conv as implicit GEMM on tf32 mma.sync.m16n8k8 (unchanged)
// ---------------------------------------------------------------------------
__global__ __launch_bounds__(128) void conv_mma_kernel(const float* __restrict__ cb) {
    __shared__ float sA[64 * 40];
    __shared__ float sB[64 * 72];

    int tid = threadIdx.x;
    int lane = tid & 31, wid = tid >> 5;
    int lg = lane >> 2;
    int lk = lane & 3;

    int p0 = blockIdx.x * 64;
    int t = p0 >> 14, h = (p0 >> 7) & 127, wbase = p0 & 127;

    float c[2][2][4];
#pragma unroll
    for (int mt = 0; mt < 2; mt++)
#pragma unroll
        for (int nt = 0; nt < 2; nt++)
#pragma unroll
            for (int r = 0; r < 4; r++) c[mt][nt][r] = 0.0f;

    for (int tap = 0; tap < 9; tap++) {
        int kh = tap / 3 - 1, kw = tap % 3 - 1;
        int hp = h + kh;
        if (hp < 0 || hp > 127) continue;
        int base = t * 16384 + hp * 128 + wbase + kw;

        for (int ic0 = 0; ic0 < 256; ic0 += 64) {
            __syncthreads();
#pragma unroll
            for (int r = 0; r < 16; r++) {
                int idx = r * 128 + tid;
                int icl = idx >> 5, o = idx & 31;
                sA[icl * 40 + o] = g_wT[(tap * 256 + ic0 + icl) * 32 + o];
            }
#pragma unroll
            for (int r = 0; r < 32; r++) {
                int idx = r * 128 + tid;
                int icl = idx >> 6, n = idx & 63;
                int wq = wbase + n + kw;
                float v = 0.0f;
                if ((unsigned)wq < 128u)
                    v = g_stacked[(ic0 + icl) * THW + base + n];
                sB[icl * 72 + n] = tf32_rna(v);
            }
            __syncthreads();

#pragma unroll
            for (int kk = 0; kk < 8; kk++) {
                int kc = kk * 8;
                unsigned a[2][4], b[2][2];
#pragma unroll
                for (int mt = 0; mt < 2; mt++) {
                    int ob = mt * 16;
                    a[mt][0] = __float_as_uint(sA[(kc + lk) * 40 + ob + lg]);
                    a[mt][1] = __float_as_uint(sA[(kc + lk) * 40 + ob + lg + 8]);
                    a[mt][2] = __float_as_uint(sA[(kc + 4 + lk) * 40 + ob + lg]);
                    a[mt][3] = __float_as_uint(sA[(kc + 4 + lk) * 40 + ob + lg + 8]);
                }
#pragma unroll
                for (int nt = 0; nt < 2; nt++) {
                    int n0 = wid * 16 + nt * 8;
                    b[nt][0] = __float_as_uint(sB[(kc + lk) * 72 + n0 + lg]);
                    b[nt][1] = __float_as_uint(sB[(kc + 4 + lk) * 72 + n0 + lg]);
                }
#pragma unroll
                for (int mt = 0; mt < 2; mt++)
#pragma unroll
                    for (int nt = 0; nt < 2; nt++) {
                        asm volatile(
                            "mma.sync.aligned.m16n8k8.row.col.f32.tf32.tf32.f32 "
                            "{%0,%1,%2,%3}, {%4,%5,%6,%7}, {%8,%9}, {%0,%1,%2,%3};"
                            : "+f"(c[mt][nt][0]), "+f"(c[mt][nt][1]),
                              "+f"(c[mt][nt][2]), "+f"(c[mt][nt][3])
                            : "r"(a[mt][0]), "r"(a[mt][1]), "r"(a[mt][2]), "r"(a[mt][3]),
                              "r"(b[nt][0]), "r"(b[nt][1]));
                    }
            }
        }
    }

#pragma unroll
    for (int mt = 0; mt < 2; mt++) {
        int r0 = mt * 16 + lg;
        float b0 = cb[r0], b1 = cb[r0 + 8];
#pragma unroll
        for (int nt = 0; nt < 2; nt++) {
            int col = wid * 16 + nt * 8 + 2 * lk;
            float2 v0 = make_float2(c[mt][nt][0] + b0, c[mt][nt][1] + b0);
            float2 v1 = make_float2(c[mt][nt][2] + b1, c[mt][nt][3] + b1);
            *(float2*)&g_x[r0 * THW + p0 + col] = v0;
            *(float2*)&g_x[(r0 + 8) * THW + p0 + col] = v1;
        }
    }
}

// ---------------------------------------------------------------------------
// Stage 3: transformer — 560-baseline (single-pass unnormalized softmax).
// ---------------------------------------------------------------------------
__device__ __forceinline__ float gelu_tanh(float a) {
    float inner = 0.7978845608028654f * fmaf(0.044715f * a, a * a, a);
    return 0.5f * a * (1.0f + tanhf(inner));
}

__global__ __launch_bounds__(128) void xf_kernel(
    const float* __restrict__ vid, float* __restrict__ out,
    const float* __restrict__ ln1_g, const float* __restrict__ ln1_b,
    const float* __restrict__ qkv_w, const float* __restrict__ qkv_b,
    const float* __restrict__ proj_w, const float* __restrict__ proj_b,
    const float* __restrict__ ln2_g, const float* __restrict__ ln2_b,
    const float* __restrict__ fc1_w, const float* __restrict__ fc1_b,
    const float* __restrict__ fc2_w, const float* __restrict__ fc2_b)
{
    extern __shared__ float sm[];
    float* s_qkvw = sm;                  // 3072
    float* s_qkvb = s_qkvw + 3072;       // 96
    float* s_projw = s_qkvb + 96;        // 1024
    float* s_projb = s_projw + 1024;     // 32
    float* s_fc1w = s_projb + 32;        // 2048
    float* s_fc1b = s_fc1w + 2048;       // 64
    float* s_fc2w = s_fc1b + 64;         // 2048
    float* s_fc2b = s_fc2w + 2048;       // 32
    float* s_g1 = s_fc2b + 32;           // 32
    float* s_b1 = s_g1 + 32;             // 32
    float* s_g2 = s_b1 + 32;             // 32
    float* s_b2 = s_g2 + 32;             // 32
    float* s_kv = s_b2 + 32;             // 2 windows x (2 x 64 x 33)

    int tid = threadIdx.x;
    int wi = tid >> 6;
    int j = tid & 63;

    float* kbuf = s_kv + wi * (2 * 64 * 33);
    float* vbuf = kbuf + 64 * 33;

    int wg = blockIdx.x * 2 + wi;
    int t = wg >> 8, nh = (wg >> 4) & 15, nw = wg & 15;
    int h = nh * 8 + (j >> 3);
    int w = nw * 8 + (j & 7);
    int p = t * 16384 + h * 128 + w;

    float xr[32];
#pragma unroll
    for (int c = 0; c < 32; c++) xr[c] = g_x[c * THW + p];

    for (int L = 0; L < 2; L++) {
        __syncthreads();
        for (int idx = tid; idx < 3072; idx += 128) s_qkvw[idx] = qkv_w[L * 3072 + idx];
        for (int idx = tid; idx < 2048; idx += 128) {
            s_fc1w[idx] = fc1_w[L * 2048 + idx];
            s_fc2w[idx] = fc2_w[L * 2048 + idx];
        }
        for (int idx = tid; idx < 1024; idx += 128) s_projw[idx] = proj_w[L * 1024 + idx];
        if (tid < 96) s_qkvb[tid] = qkv_b[L * 96 + tid];
        if (tid < 64) s_fc1b[tid] = fc1_b[L * 64 + tid];
        if (tid < 32) {
            s_projb[tid] = proj_b[L * 32 + tid];
            s_fc2b[tid] = fc2_b[L * 32 + tid];
            s_g1[tid] = ln1_g[L * 32 + tid];
            s_b1[tid] = ln1_b[L * 32 + tid];
            s_g2[tid] = ln2_g[L * 32 + tid];
            s_b2[tid] = ln2_b[L * 32 + tid];
        }
        __syncthreads();

        float mu = 0.0f;
#pragma unroll
        for (int c = 0; c < 32; c++) mu += xr[c];
        mu *= 0.03125f;
        float var = 0.0f;
#pragma unroll
        for (int c = 0; c < 32; c++) { float d = xr[c] - mu; var = fmaf(d, d, var); }
        var *= 0.03125f;
        float rstd = rsqrtf(var + 1e-5f);
        float hv[32];
#pragma unroll
        for (int c = 0; c < 32; c++) hv[c] = (xr[c] - mu) * rstd * s_g1[c] + s_b1[c];

        float q[32];
#pragma unroll
        for (int jq = 0; jq < 32; jq++) {
            float s = s_qkvb[jq];
#pragma unroll
            for (int c = 0; c < 32; c++) s = fmaf(hv[c], s_qkvw[c * 96 + jq], s);
            q[jq] = s;
        }
        for (int jk = 0; jk < 32; jk++) {
            float s = s_qkvb[32 + jk];
#pragma unroll
            for (int c = 0; c < 32; c++) s = fmaf(hv[c], s_qkvw[c * 96 + 32 + jk], s);
            kbuf[j * 33 + jk] = s;
        }
        for (int jv = 0; jv < 32; jv++) {
            float s = s_qkvb[64 + jv];
#pragma unroll
            for (int c = 0; c < 32; c++) s = fmaf(hv[c], s_qkvw[c * 96 + 64 + jv], s);
            vbuf[j * 33 + jv] = s;
        }
        __syncthreads();

        // ---- attention: single pass, unnormalized softmax ----
        float ov[32];
        const float scale = 0.3535533905932738f;
#pragma unroll
        for (int hh = 0; hh < 4; hh++) {
            const int base = hh * 8;
            float sum = 0.0f;
            float o0 = 0, o1 = 0, o2 = 0, o3 = 0, o4 = 0, o5 = 0, o6 = 0, o7 = 0;
            for (int kk = 0; kk < 64; kk++) {
                float s = 0.0f;
#pragma unroll
                for (int d = 0; d < 8; d++) s = fmaf(q[base + d], kbuf[kk * 33 + base + d], s);
                float e = __expf(s * scale);
                sum += e;
                o0 = fmaf(e, vbuf[kk * 33 + base + 0], o0);
                o1 = fmaf(e, vbuf[kk * 33 + base + 1], o1);
                o2 = fmaf(e, vbuf[kk * 33 + base + 2], o2);
                o3 = fmaf(e, vbuf[kk * 33 + base + 3], o3);
                o4 = fmaf(e, vbuf[kk * 33 + base + 4], o4);
                o5 = fmaf(e, vbuf[kk * 33 + base + 5], o5);
                o6 = fmaf(e, vbuf[kk * 33 + base + 6], o6);
                o7 = fmaf(e, vbuf[kk * 33 + base + 7], o7);
            }
            float inv = 1.0f / sum;
            ov[base + 0] = o0 * inv; ov[base + 1] = o1 * inv;
            ov[base + 2] = o2 * inv; ov[base + 3] = o3 * inv;
            ov[base + 4] = o4 * inv; ov[base + 5] = o5 * inv;
            ov[base + 6] = o6 * inv; ov[base + 7] = o7 * inv;
        }

#pragma unroll
        for (int c = 0; c < 32; c++) {
            float s = s_projb[c];
#pragma unroll
            for (int u = 0; u < 32; u++) s = fmaf(ov[u], s_projw[u * 32 + c], s);
            xr[c] += s;
        }

        mu = 0.0f;
#pragma unroll
        for (int c = 0; c < 32; c++) mu += xr[c];
        mu *= 0.03125f;
        var = 0.0f;
#pragma unroll
        for (int c = 0; c < 32; c++) { float d = xr[c] - mu; var = fmaf(d, d, var); }
        var *= 0.03125f;
        rstd = rsqrtf(var + 1e-5f);
#pragma unroll
        for (int c = 0; c < 32; c++) hv[c] = (xr[c] - mu) * rstd * s_g2[c] + s_b2[c];

        float acc[32];
#pragma unroll
        for (int c = 0; c < 32; c++) acc[c] = 0.0f;
        for (int u = 0; u < 64; u++) {
            float a = s_fc1b[u];
#pragma unroll
            for (int c = 0; c < 32; c++) a = fmaf(hv[c], s_fc1w[c * 64 + u], a);
            float g = gelu_tanh(a);
#pragma unroll
            for (int c = 0; c < 32; c++) acc[c] = fmaf(g, s_fc2w[u * 32 + c], acc[c]);
        }
#pragma unroll
        for (int c = 0; c < 32; c++) xr[c] += acc[c] + s_fc2b[c];
    }

#pragma unroll
    for (int c = 0; c < 32; c++) out[c * THW + p] = vid[c * THW + p] + xr[c];
}

// ---------------------------------------------------------------------------
extern "C" void kernel_launch(void* const* d_in, const int* in_sizes, int n_in,
                              void* d_out, int out_size) {
    const float* vid    = (const float*)d_in[0];
    const float* conv_w = (const float*)d_in[1];
    const float* conv_b = (const float*)d_in[2];
    const float* ln1_g  = (const float*)d_in[3];
    const float* ln1_b  = (const float*)d_in[4];
    const float* qkv_w  = (const float*)d_in[5];
    const float* qkv_b  = (const float*)d_in[6];
    const float* proj_w = (const float*)d_in[7];
    const float* proj_b = (const float*)d_in[8];
    const float* ln2_g  = (const float*)d_in[9];
    const float* ln2_b  = (const float*)d_in[10];
    const float* fc1_w  = (const float*)d_in[11];
    const float* fc1_b  = (const float*)d_in[12];
    const float* fc2_w  = (const float*)d_in[13];
    const float* fc2_b  = (const float*)d_in[14];
    float* out = (float*)d_out;

    nl_stack_kernel<<<256, 128>>>(vid);      // 2 h-adjacent voxels per thread
    wT_kernel<<<576, 128>>>(conv_w);
    conv_mma_kernel<<<1024, 128>>>(conv_b);

    const int smem_bytes = (8544 + 2 * 2 * 64 * 33) * (int)sizeof(float);  // 67968
    cudaFuncSetAttribute(xf_kernel, cudaFuncAttributeMaxDynamicSharedMemorySize, smem_bytes);
    xf_kernel<<<512, 128, smem_bytes>>>(vid, out,
                                        ln1_g, ln1_b, qkv_w, qkv_b, proj_w, proj_b,
                                        ln2_g, ln2_b, fc1_w, fc1_b, fc2_w, fc2_b);
}

// round 14
// speedup vs baseline: 1.2318x; 1.2318x over previous
#include <cuda_runtime.h>
#include <math.h>

#define THW 65536
#define C_ 32
#define KNN 8

// Scratch (allowed: __device__ globals, no allocation)
__device__ float g_stacked[256 * THW];   // 64 MB: [k*C+c][THW]
__device__ float g_x[C_ * THW];          // 8 MB : conv output [C][THW]
__device__ float g_wT[9 * 256 * 32];     // tf32-rounded conv weights [tap][ic][o]

__device__ __forceinline__ float tf32_rna(float v) {
    unsigned u;
    asm("cvt.rna.tf32.f32 %0, %1;" : "=r"(u) : "f"(v));
    return __uint_as_float(u);
}

// ---------------------------------------------------------------------------
// Stage 1: non-local kNN search, 2 threads per voxel (round-11 best: restored)
// ---------------------------------------------------------------------------
__global__ __launch_bounds__(128) void nl_stack_kernel(const float* __restrict__ vid) {
    int gtid = blockIdx.x * 128 + threadIdx.x;
    int p = gtid >> 1;
    int half = gtid & 1;
    int t = p >> 14;
    int h = (p >> 7) & 127;
    int w = p & 127;

    float x[C_];
#pragma unroll
    for (int c = 0; c < C_; c++) x[c] = vid[c * THW + p];

    float bd[KNN];
    int   bq[KNN];
#pragma unroll
    for (int k = 0; k < KNN; k++) { bd[k] = 3.4e38f; bq[k] = 0; }

    int obase = half ? 122 : 0;
    int niter = half ? 121 : 122;
    for (int i = 0; i < niter; i++) {
        int o = obase + i;
        int dt = o / 81;
        int r  = o - dt * 81;
        int dh = r / 9;
        int dw = r - dh * 9;
        int ti = t + dt - 1; ti = ti < 0 ? 0 : (ti > 3 ? 3 : ti);
        int hi = h + dh - 4; hi = hi < 0 ? 0 : (hi > 127 ? 127 : hi);
        int wi = w + dw - 4; wi = wi < 0 ? 0 : (wi > 127 ? 127 : wi);
        int q = ti * 16384 + hi * 128 + wi;
        float d0 = 0.0f, d1 = 0.0f, d2 = 0.0f, d3 = 0.0f;
#pragma unroll
        for (int c = 0; c < C_; c += 4) {
            float a0 = x[c + 0] - vid[(c + 0) * THW + q];
            float a1 = x[c + 1] - vid[(c + 1) * THW + q];
            float a2 = x[c + 2] - vid[(c + 2) * THW + q];
            float a3 = x[c + 3] - vid[(c + 3) * THW + q];
            d0 = fmaf(a0, a0, d0);
            d1 = fmaf(a1, a1, d1);
            d2 = fmaf(a2, a2, d2);
            d3 = fmaf(a3, a3, d3);
        }
        float d = (d0 + d1) + (d2 + d3);
        if (d < bd[KNN - 1]) {
            int ins = KNN - 1;
#pragma unroll
            for (int k = KNN - 2; k >= 0; k--) {
                if (d < bd[k]) { bd[k + 1] = bd[k]; bq[k + 1] = bq[k]; ins = k; }
            }
            bd[ins] = d; bq[ins] = q;
        }
    }

    float md[16]; int mq[16];
#pragma unroll
    for (int k = 0; k < 8; k++) { md[k] = bd[k]; mq[k] = bq[k]; }
#pragma unroll
    for (int k = 0; k < 8; k++) {
        md[8 + k] = __shfl_xor_sync(0xffffffffu, bd[7 - k], 1);
        mq[8 + k] = __shfl_xor_sync(0xffffffffu, bq[7 - k], 1);
    }
#pragma unroll
    for (int dlt = 8; dlt >= 1; dlt >>= 1) {
#pragma unroll
        for (int i = 0; i < 16; i++) {
            if ((i & dlt) == 0) {
                float da = md[i], db = md[i + dlt];
                int   qa = mq[i], qb = mq[i + dlt];
                bool sw = db < da;
                md[i]       = sw ? db : da;
                md[i + dlt] = sw ? da : db;
                mq[i]       = sw ? qb : qa;
                mq[i + dlt] = sw ? qa : qb;
            }
        }
    }

    float e0 = __expf(md[0] - md[0]), e1 = __expf(md[0] - md[1]);
    float e2 = __expf(md[0] - md[2]), e3 = __expf(md[0] - md[3]);
    float e4 = __expf(md[0] - md[4]), e5 = __expf(md[0] - md[5]);
    float e6 = __expf(md[0] - md[6]), e7 = __expf(md[0] - md[7]);
    float sum = ((e0 + e1) + (e2 + e3)) + ((e4 + e5) + (e6 + e7));
    float inv = 1.0f / sum;

    int kbase = half * 4;
#pragma unroll
    for (int kk = 0; kk < 4; kk++) {
        float ek;
        int qk;
        switch (kk) {
            case 0: ek = half ? e4 : e0; qk = half ? mq[4] : mq[0]; break;
            case 1: ek = half ? e5 : e1; qk = half ? mq[5] : mq[1]; break;
            case 2: ek = half ? e6 : e2; qk = half ? mq[6] : mq[2]; break;
            default: ek = half ? e7 : e3; qk = half ? mq[7] : mq[3]; break;
        }
        float wk = ek * inv;
#pragma unroll
        for (int c = 0; c < C_; c++) {
            g_stacked[((kbase + kk) * C_ + c) * THW + p] = vid[c * THW + qk] * wk;
        }
    }
}

// ---------------------------------------------------------------------------
// Weight pre-transform (unchanged)
// ---------------------------------------------------------------------------
__global__ __launch_bounds__(128) void wT_kernel(const float* __restrict__ cw) {
    int i = blockIdx.x * 128 + threadIdx.x;
    int o = i & 31;
    int ic = (i >> 5) & 255;
    int tap = i >> 13;
    g_wT[i] = tf32_rna(cw[(o * 256 + ic) * 9 + tap]);
}

// ---------------------------------------------------------------------------
// Stage 2: conv implicit GEMM, cp.async DOUBLE-BUFFERED pipeline.
// 36 uniform chunks (9 taps x 4 ic-chunks); invalid edge taps stage from a
// clamped address and skip the MMA. tf32 conversion of B moved to fragment
// load (same bits into MMA as before).
// Buffers: sA 64x40, sB 64x72 floats, x2 = 57344 B dynamic smem.
// ---------------------------------------------------------------------------
#define SA_FLOATS (64 * 40)
#define SB_FLOATS (64 * 72)
#define BUF_FLOATS (SA_FLOATS + SB_FLOATS)

__device__ __forceinline__ void conv_stage_chunk(
    float* sA, float* sB, int tap, int ic0, int t, int h, int wbase, int tid)
{
    int kh = tap / 3 - 1, kw = tap % 3 - 1;
    int hp = h + kh; hp = hp < 0 ? 0 : (hp > 127 ? 127 : hp);   // clamped (valid-tap check at MMA)
    int base = t * 16384 + hp * 128 + wbase + kw;
    // sA: 512 x 16B copies (4/thread). smem rows 160B, gmem rows 128B: both 16B-aligned.
#pragma unroll
    for (int r = 0; r < 4; r++) {
        int idx = r * 128 + tid;            // 0..511
        int icl = idx >> 3, seg = idx & 7;
        const float* src = &g_wT[(tap * 256 + ic0 + icl) * 32 + seg * 4];
        unsigned daddr = (unsigned)__cvta_generic_to_shared(&sA[icl * 40 + seg * 4]);
        asm volatile("cp.async.ca.shared.global [%0], [%1], 16;" :: "r"(daddr), "l"(src) : "memory");
    }
    // sB: 4096 x 4B copies (32/thread); OOB w columns zeroed via STS.
#pragma unroll
    for (int r = 0; r < 32; r++) {
        int idx = r * 128 + tid;
        int icl = idx >> 6, n = idx & 63;
        int wq = wbase + n + kw;
        unsigned daddr = (unsigned)__cvta_generic_to_shared(&sB[icl * 72 + n]);
        if ((unsigned)wq < 128u) {
            const float* src = &g_stacked[(ic0 + icl) * THW + base + n];
            asm volatile("cp.async.ca.shared.global [%0], [%1], 4;" :: "r"(daddr), "l"(src) : "memory");
        } else {
            asm volatile("st.shared.b32 [%0], %1;" :: "r"(daddr), "r"(0) : "memory");
        }
    }
}

__global__ __launch_bounds__(128) void conv_mma_kernel(const float* __restrict__ cb) {
    extern __shared__ float cbuf[];
    float* sAb[2] = {cbuf, cbuf + BUF_FLOATS};
    float* sBb[2] = {cbuf + SA_FLOATS, cbuf + BUF_FLOATS + SA_FLOATS};

    int tid = threadIdx.x;
    int lane = tid & 31, wid = tid >> 5;
    int lg = lane >> 2;
    int lk = lane & 3;

    int p0 = blockIdx.x * 64;
    int t = p0 >> 14, h = (p0 >> 7) & 127, wbase = p0 & 127;

    float c[2][2][4];
#pragma unroll
    for (int mt = 0; mt < 2; mt++)
#pragma unroll
        for (int nt = 0; nt < 2; nt++)
#pragma unroll
            for (int r = 0; r < 4; r++) c[mt][nt][r] = 0.0f;

    // prologue: stage chunk 0
    conv_stage_chunk(sAb[0], sBb[0], 0, 0, t, h, wbase, tid);
    asm volatile("cp.async.commit_group;" ::: "memory");

    for (int i = 0; i < 36; i++) {
        int tap = i >> 2, ic0 = (i & 3) << 6;
        if (i < 35) {
            int tn = (i + 1) >> 2, icn = ((i + 1) & 3) << 6;
            conv_stage_chunk(sAb[(i + 1) & 1], sBb[(i + 1) & 1], tn, icn, t, h, wbase, tid);
            asm volatile("cp.async.commit_group;" ::: "memory");
            asm volatile("cp.async.wait_group 1;" ::: "memory");
        } else {
            asm volatile("cp.async.wait_group 0;" ::: "memory");
        }
        __syncthreads();

        int kh = tap / 3 - 1;
        int hpv = h + kh;
        if (hpv >= 0 && hpv <= 127) {                    // uniform per CTA
            float* sA = sAb[i & 1];
            float* sB = sBb[i & 1];
#pragma unroll
            for (int kk = 0; kk < 8; kk++) {
                int kc = kk * 8;
                unsigned a[2][4], b[2][2];
#pragma unroll
                for (int mt = 0; mt < 2; mt++) {
                    int ob = mt * 16;
                    a[mt][0] = __float_as_uint(sA[(kc + lk) * 40 + ob + lg]);
                    a[mt][1] = __float_as_uint(sA[(kc + lk) * 40 + ob + lg + 8]);
                    a[mt][2] = __float_as_uint(sA[(kc + 4 + lk) * 40 + ob + lg]);
                    a[mt][3] = __float_as_uint(sA[(kc + 4 + lk) * 40 + ob + lg + 8]);
                }
#pragma unroll
                for (int nt = 0; nt < 2; nt++) {
                    int n0 = wid * 16 + nt * 8;
                    b[nt][0] = __float_as_uint(tf32_rna(sB[(kc + lk) * 72 + n0 + lg]));
                    b[nt][1] = __float_as_uint(tf32_rna(sB[(kc + 4 + lk) * 72 + n0 + lg]));
                }
#pragma unroll
                for (int mt = 0; mt < 2; mt++)
#pragma unroll
                    for (int nt = 0; nt < 2; nt++) {
                        asm volatile(
                            "mma.sync.aligned.m16n8k8.row.col.f32.tf32.tf32.f32 "
                            "{%0,%1,%2,%3}, {%4,%5,%6,%7}, {%8,%9}, {%0,%1,%2,%3};"
                            : "+f"(c[mt][nt][0]), "+f"(c[mt][nt][1]),
                              "+f"(c[mt][nt][2]), "+f"(c[mt][nt][3])
                            : "r"(a[mt][0]), "r"(a[mt][1]), "r"(a[mt][2]), "r"(a[mt][3]),
                              "r"(b[nt][0]), "r"(b[nt][1]));
                    }
            }
        }
        __syncthreads();   // all reads done before next stage overwrites this buffer
    }

    // epilogue: D[m][n] -> g_x[m*THW + p0+n], + bias
#pragma unroll
    for (int mt = 0; mt < 2; mt++) {
        int r0 = mt * 16 + lg;
        float b0 = cb[r0], b1 = cb[r0 + 8];
#pragma unroll
        for (int nt = 0; nt < 2; nt++) {
            int col = wid * 16 + nt * 8 + 2 * lk;
            float2 v0 = make_float2(c[mt][nt][0] + b0, c[mt][nt][1] + b0);
            float2 v1 = make_float2(c[mt][nt][2] + b1, c[mt][nt][3] + b1);
            *(float2*)&g_x[r0 * THW + p0 + col] = v0;
            *(float2*)&g_x[(r0 + 8) * THW + p0 + col] = v1;
        }
    }
}

// ---------------------------------------------------------------------------
// Stage 3: transformer — 560-baseline (single-pass unnormalized softmax).
// ---------------------------------------------------------------------------
__device__ __forceinline__ float gelu_tanh(float a) {
    float inner = 0.7978845608028654f * fmaf(0.044715f * a, a * a, a);
    return 0.5f * a * (1.0f + tanhf(inner));
}

__global__ __launch_bounds__(128) void xf_kernel(
    const float* __restrict__ vid, float* __restrict__ out,
    const float* __restrict__ ln1_g, const float* __restrict__ ln1_b,
    const float* __restrict__ qkv_w, const float* __restrict__ qkv_b,
    const float* __restrict__ proj_w, const float* __restrict__ proj_b,
    const float* __restrict__ ln2_g, const float* __restrict__ ln2_b,
    const float* __restrict__ fc1_w, const float* __restrict__ fc1_b,
    const float* __restrict__ fc2_w, const float* __restrict__ fc2_b)
{
    extern __shared__ float sm[];
    float* s_qkvw = sm;                  // 3072
    float* s_qkvb = s_qkvw + 3072;       // 96
    float* s_projw = s_qkvb + 96;        // 1024
    float* s_projb = s_projw + 1024;     // 32
    float* s_fc1w = s_projb + 32;        // 2048
    float* s_fc1b = s_fc1w + 2048;       // 64
    float* s_fc2w = s_fc1b + 64;         // 2048
    float* s_fc2b = s_fc2w + 2048;       // 32
    float* s_g1 = s_fc2b + 32;           // 32
    float* s_b1 = s_g1 + 32;             // 32
    float* s_g2 = s_b1 + 32;             // 32
    float* s_b2 = s_g2 + 32;             // 32
    float* s_kv = s_b2 + 32;             // 2 windows x (2 x 64 x 33)

    int tid = threadIdx.x;
    int wi = tid >> 6;
    int j = tid & 63;

    float* kbuf = s_kv + wi * (2 * 64 * 33);
    float* vbuf = kbuf + 64 * 33;

    int wg = blockIdx.x * 2 + wi;
    int t = wg >> 8, nh = (wg >> 4) & 15, nw = wg & 15;
    int h = nh * 8 + (j >> 3);
    int w = nw * 8 + (j & 7);
    int p = t * 16384 + h * 128 + w;

    float xr[32];
#pragma unroll
    for (int c = 0; c < 32; c++) xr[c] = g_x[c * THW + p];

    for (int L = 0; L < 2; L++) {
        __syncthreads();
        for (int idx = tid; idx < 3072; idx += 128) s_qkvw[idx] = qkv_w[L * 3072 + idx];
        for (int idx = tid; idx < 2048; idx += 128) {
            s_fc1w[idx] = fc1_w[L * 2048 + idx];
            s_fc2w[idx] = fc2_w[L * 2048 + idx];
        }
        for (int idx = tid; idx < 1024; idx += 128) s_projw[idx] = proj_w[L * 1024 + idx];
        if (tid < 96) s_qkvb[tid] = qkv_b[L * 96 + tid];
        if (tid < 64) s_fc1b[tid] = fc1_b[L * 64 + tid];
        if (tid < 32) {
            s_projb[tid] = proj_b[L * 32 + tid];
            s_fc2b[tid] = fc2_b[L * 32 + tid];
            s_g1[tid] = ln1_g[L * 32 + tid];
            s_b1[tid] = ln1_b[L * 32 + tid];
            s_g2[tid] = ln2_g[L * 32 + tid];
            s_b2[tid] = ln2_b[L * 32 + tid];
        }
        __syncthreads();

        float mu = 0.0f;
#pragma unroll
        for (int c = 0; c < 32; c++) mu += xr[c];
        mu *= 0.03125f;
        float var = 0.0f;
#pragma unroll
        for (int c = 0; c < 32; c++) { float d = xr[c] - mu; var = fmaf(d, d, var); }
        var *= 0.03125f;
        float rstd = rsqrtf(var + 1e-5f);
        float hv[32];
#pragma unroll
        for (int c = 0; c < 32; c++) hv[c] = (xr[c] - mu) * rstd * s_g1[c] + s_b1[c];

        float q[32];
#pragma unroll
        for (int jq = 0; jq < 32; jq++) {
            float s = s_qkvb[jq];
#pragma unroll
            for (int c = 0; c < 32; c++) s = fmaf(hv[c], s_qkvw[c * 96 + jq], s);
            q[jq] = s;
        }
        for (int jk = 0; jk < 32; jk++) {
            float s = s_qkvb[32 + jk];
#pragma unroll
            for (int c = 0; c < 32; c++) s = fmaf(hv[c], s_qkvw[c * 96 + 32 + jk], s);
            kbuf[j * 33 + jk] = s;
        }
        for (int jv = 0; jv < 32; jv++) {
            float s = s_qkvb[64 + jv];
#pragma unroll
            for (int c = 0; c < 32; c++) s = fmaf(hv[c], s_qkvw[c * 96 + 64 + jv], s);
            vbuf[j * 33 + jv] = s;
        }
        __syncthreads();

        float ov[32];
        const float scale = 0.3535533905932738f;
#pragma unroll
        for (int hh = 0; hh < 4; hh++) {
            const int base = hh * 8;
            float sum = 0.0f;
            float o0 = 0, o1 = 0, o2 = 0, o3 = 0, o4 = 0, o5 = 0, o6 = 0, o7 = 0;
            for (int kk = 0; kk < 64; kk++) {
                float s = 0.0f;
#pragma unroll
                for (int d = 0; d < 8; d++) s = fmaf(q[base + d], kbuf[kk * 33 + base + d], s);
                float e = __expf(s * scale);
                sum += e;
                o0 = fmaf(e, vbuf[kk * 33 + base + 0], o0);
                o1 = fmaf(e, vbuf[kk * 33 + base + 1], o1);
                o2 = fmaf(e, vbuf[kk * 33 + base + 2], o2);
                o3 = fmaf(e, vbuf[kk * 33 + base + 3], o3);
                o4 = fmaf(e, vbuf[kk * 33 + base + 4], o4);
                o5 = fmaf(e, vbuf[kk * 33 + base + 5], o5);
                o6 = fmaf(e, vbuf[kk * 33 + base + 6], o6);
                o7 = fmaf(e, vbuf[kk * 33 + base + 7], o7);
            }
            float inv = 1.0f / sum;
            ov[base + 0] = o0 * inv; ov[base + 1] = o1 * inv;
            ov[base + 2] = o2 * inv; ov[base + 3] = o3 * inv;
            ov[base + 4] = o4 * inv; ov[base + 5] = o5 * inv;
            ov[base + 6] = o6 * inv; ov[base + 7] = o7 * inv;
        }

#pragma unroll
        for (int c = 0; c < 32; c++) {
            float s = s_projb[c];
#pragma unroll
            for (int u = 0; u < 32; u++) s = fmaf(ov[u], s_projw[u * 32 + c], s);
            xr[c] += s;
        }

        mu = 0.0f;
#pragma unroll
        for (int c = 0; c < 32; c++) mu += xr[c];
        mu *= 0.03125f;
        var = 0.0f;
#pragma unroll
        for (int c = 0; c < 32; c++) { float d = xr[c] - mu; var = fmaf(d, d, var); }
        var *= 0.03125f;
        rstd = rsqrtf(var + 1e-5f);
#pragma unroll
        for (int c = 0; c < 32; c++) hv[c] = (xr[c] - mu) * rstd * s_g2[c] + s_b2[c];

        float acc[32];
#pragma unroll
        for (int c = 0; c < 32; c++) acc[c] = 0.0f;
        for (int u = 0; u < 64; u++) {
            float a = s_fc1b[u];
#pragma unroll
            for (int c = 0; c < 32; c++) a = fmaf(hv[c], s_fc1w[c * 64 + u], a);
            float g = gelu_tanh(a);
#pragma unroll
            for (int c = 0; c < 32; c++) acc[c] = fmaf(g, s_fc2w[u * 32 + c], acc[c]);
        }
#pragma unroll
        for (int c = 0; c < 32; c++) xr[c] += acc[c] + s_fc2b[c];
    }

#pragma unroll
    for (int c = 0; c < 32; c++) out[c * THW + p] = vid[c * THW + p] + xr[c];
}

// ---------------------------------------------------------------------------
extern "C" void kernel_launch(void* const* d_in, const int* in_sizes, int n_in,
                              void* d_out, int out_size) {
    const float* vid    = (const float*)d_in[0];
    const float* conv_w = (const float*)d_in[1];
    const float* conv_b = (const float*)d_in[2];
    const float* ln1_g  = (const float*)d_in[3];
    const float* ln1_b  = (const float*)d_in[4];
    const float* qkv_w  = (const float*)d_in[5];
    const float* qkv_b  = (const float*)d_in[6];
    const float* proj_w = (const float*)d_in[7];
    const float* proj_b = (const float*)d_in[8];
    const float* ln2_g  = (const float*)d_in[9];
    const float* ln2_b  = (const float*)d_in[10];
    const float* fc1_w  = (const float*)d_in[11];
    const float* fc1_b  = (const float*)d_in[12];
    const float* fc2_w  = (const float*)d_in[13];
    const float* fc2_b  = (const float*)d_in[14];
    float* out = (float*)d_out;

    nl_stack_kernel<<<1024, 128>>>(vid);      // 2 threads per voxel (560-base)
    wT_kernel<<<576, 128>>>(conv_w);

    const int conv_smem = 2 * BUF_FLOATS * (int)sizeof(float);  // 57344
    cudaFuncSetAttribute(conv_mma_kernel, cudaFuncAttributeMaxDynamicSharedMemorySize, conv_smem);
    conv_mma_kernel<<<1024, 128, conv_smem>>>(conv_b);

    const int smem_bytes = (8544 + 2 * 2 * 64 * 33) * (int)sizeof(float);  // 67968
    cudaFuncSetAttribute(xf_kernel, cudaFuncAttributeMaxDynamicSharedMemorySize, smem_bytes);
    xf_kernel<<<512, 128, smem_bytes>>>(vid, out,
                                        ln1_g, ln1_b, qkv_w, qkv_b, proj_w, proj_b,
                                        ln2_g, ln2_b, fc1_w, fc1_b, fc2_w, fc2_b);
}

// round 15
// speedup vs baseline: 1.3910x; 1.1292x over previous
#include <cuda_runtime.h>
#include <math.h>

#define THW 65536
#define C_ 32
#define KNN 8

// Scratch (allowed: __device__ globals, no allocation)
__device__ float g_stacked[256 * THW];   // 64 MB: [k*C+c][THW]
__device__ float g_x[C_ * THW];          // 8 MB : conv output [C][THW]
__device__ float g_wT[9 * 256 * 32];     // tf32-rounded conv weights [tap][ic][o]

__device__ __forceinline__ float tf32_rna(float v) {
    unsigned u;
    asm("cvt.rna.tf32.f32 %0, %1;" : "=r"(u) : "f"(v));
    return __uint_as_float(u);
}

// ---------------------------------------------------------------------------
// Stage 1: non-local kNN search, 2 threads per voxel (560-base, unchanged)
// ---------------------------------------------------------------------------
__global__ __launch_bounds__(128) void nl_stack_kernel(const float* __restrict__ vid) {
    int gtid = blockIdx.x * 128 + threadIdx.x;
    int p = gtid >> 1;
    int half = gtid & 1;
    int t = p >> 14;
    int h = (p >> 7) & 127;
    int w = p & 127;

    float x[C_];
#pragma unroll
    for (int c = 0; c < C_; c++) x[c] = vid[c * THW + p];

    float bd[KNN];
    int   bq[KNN];
#pragma unroll
    for (int k = 0; k < KNN; k++) { bd[k] = 3.4e38f; bq[k] = 0; }

    int obase = half ? 122 : 0;
    int niter = half ? 121 : 122;
    for (int i = 0; i < niter; i++) {
        int o = obase + i;
        int dt = o / 81;
        int r  = o - dt * 81;
        int dh = r / 9;
        int dw = r - dh * 9;
        int ti = t + dt - 1; ti = ti < 0 ? 0 : (ti > 3 ? 3 : ti);
        int hi = h + dh - 4; hi = hi < 0 ? 0 : (hi > 127 ? 127 : hi);
        int wi = w + dw - 4; wi = wi < 0 ? 0 : (wi > 127 ? 127 : wi);
        int q = ti * 16384 + hi * 128 + wi;
        float d0 = 0.0f, d1 = 0.0f, d2 = 0.0f, d3 = 0.0f;
#pragma unroll
        for (int c = 0; c < C_; c += 4) {
            float a0 = x[c + 0] - vid[(c + 0) * THW + q];
            float a1 = x[c + 1] - vid[(c + 1) * THW + q];
            float a2 = x[c + 2] - vid[(c + 2) * THW + q];
            float a3 = x[c + 3] - vid[(c + 3) * THW + q];
            d0 = fmaf(a0, a0, d0);
            d1 = fmaf(a1, a1, d1);
            d2 = fmaf(a2, a2, d2);
            d3 = fmaf(a3, a3, d3);
        }
        float d = (d0 + d1) + (d2 + d3);
        if (d < bd[KNN - 1]) {
            int ins = KNN - 1;
#pragma unroll
            for (int k = KNN - 2; k >= 0; k--) {
                if (d < bd[k]) { bd[k + 1] = bd[k]; bq[k + 1] = bq[k]; ins = k; }
            }
            bd[ins] = d; bq[ins] = q;
        }
    }

    float md[16]; int mq[16];
#pragma unroll
    for (int k = 0; k < 8; k++) { md[k] = bd[k]; mq[k] = bq[k]; }
#pragma unroll
    for (int k = 0; k < 8; k++) {
        md[8 + k] = __shfl_xor_sync(0xffffffffu, bd[7 - k], 1);
        mq[8 + k] = __shfl_xor_sync(0xffffffffu, bq[7 - k], 1);
    }
#pragma unroll
    for (int dlt = 8; dlt >= 1; dlt >>= 1) {
#pragma unroll
        for (int i = 0; i < 16; i++) {
            if ((i & dlt) == 0) {
                float da = md[i], db = md[i + dlt];
                int   qa = mq[i], qb = mq[i + dlt];
                bool sw = db < da;
                md[i]       = sw ? db : da;
                md[i + dlt] = sw ? da : db;
                mq[i]       = sw ? qb : qa;
                mq[i + dlt] = sw ? qa : qb;
            }
        }
    }

    float e0 = __expf(md[0] - md[0]), e1 = __expf(md[0] - md[1]);
    float e2 = __expf(md[0] - md[2]), e3 = __expf(md[0] - md[3]);
    float e4 = __expf(md[0] - md[4]), e5 = __expf(md[0] - md[5]);
    float e6 = __expf(md[0] - md[6]), e7 = __expf(md[0] - md[7]);
    float sum = ((e0 + e1) + (e2 + e3)) + ((e4 + e5) + (e6 + e7));
    float inv = 1.0f / sum;

    int kbase = half * 4;
#pragma unroll
    for (int kk = 0; kk < 4; kk++) {
        float ek;
        int qk;
        switch (kk) {
            case 0: ek = half ? e4 : e0; qk = half ? mq[4] : mq[0]; break;
            case 1: ek = half ? e5 : e1; qk = half ? mq[5] : mq[1]; break;
            case 2: ek = half ? e6 : e2; qk = half ? mq[6] : mq[2]; break;
            default: ek = half ? e7 : e3; qk = half ? mq[7] : mq[3]; break;
        }
        float wk = ek * inv;
#pragma unroll
        for (int c = 0; c < C_; c++) {
            g_stacked[((kbase + kk) * C_ + c) * THW + p] = vid[c * THW + qk] * wk;
        }
    }
}

// ---------------------------------------------------------------------------
// Weight pre-transform (unchanged)
// ---------------------------------------------------------------------------
__global__ __launch_bounds__(128) void wT_kernel(const float* __restrict__ cw) {
    int i = blockIdx.x * 128 + threadIdx.x;
    int o = i & 31;
    int ic = (i >> 5) & 255;
    int tap = i >> 13;
    g_wT[i] = tf32_rna(cw[(o * 256 + ic) * 9 + tap]);
}

// ---------------------------------------------------------------------------
// Stage 2: conv implicit GEMM (560-base simple version: REVERTED from cp.async)
// ---------------------------------------------------------------------------
__global__ __launch_bounds__(128) void conv_mma_kernel(const float* __restrict__ cb) {
    __shared__ float sA[64 * 40];
    __shared__ float sB[64 * 72];

    int tid = threadIdx.x;
    int lane = tid & 31, wid = tid >> 5;
    int lg = lane >> 2;
    int lk = lane & 3;

    int p0 = blockIdx.x * 64;
    int t = p0 >> 14, h = (p0 >> 7) & 127, wbase = p0 & 127;

    float c[2][2][4];
#pragma unroll
    for (int mt = 0; mt < 2; mt++)
#pragma unroll
        for (int nt = 0; nt < 2; nt++)
#pragma unroll
            for (int r = 0; r < 4; r++) c[mt][nt][r] = 0.0f;

    for (int tap = 0; tap < 9; tap++) {
        int kh = tap / 3 - 1, kw = tap % 3 - 1;
        int hp = h + kh;
        if (hp < 0 || hp > 127) continue;
        int base = t * 16384 + hp * 128 + wbase + kw;

        for (int ic0 = 0; ic0 < 256; ic0 += 64) {
            __syncthreads();
#pragma unroll
            for (int r = 0; r < 16; r++) {
                int idx = r * 128 + tid;
                int icl = idx >> 5, o = idx & 31;
                sA[icl * 40 + o] = g_wT[(tap * 256 + ic0 + icl) * 32 + o];
            }
#pragma unroll
            for (int r = 0; r < 32; r++) {
                int idx = r * 128 + tid;
                int icl = idx >> 6, n = idx & 63;
                int wq = wbase + n + kw;
                float v = 0.0f;
                if ((unsigned)wq < 128u)
                    v = g_stacked[(ic0 + icl) * THW + base + n];
                sB[icl * 72 + n] = tf32_rna(v);
            }
            __syncthreads();

#pragma unroll
            for (int kk = 0; kk < 8; kk++) {
                int kc = kk * 8;
                unsigned a[2][4], b[2][2];
#pragma unroll
                for (int mt = 0; mt < 2; mt++) {
                    int ob = mt * 16;
                    a[mt][0] = __float_as_uint(sA[(kc + lk) * 40 + ob + lg]);
                    a[mt][1] = __float_as_uint(sA[(kc + lk) * 40 + ob + lg + 8]);
                    a[mt][2] = __float_as_uint(sA[(kc + 4 + lk) * 40 + ob + lg]);
                    a[mt][3] = __float_as_uint(sA[(kc + 4 + lk) * 40 + ob + lg + 8]);
                }
#pragma unroll
                for (int nt = 0; nt < 2; nt++) {
                    int n0 = wid * 16 + nt * 8;
                    b[nt][0] = __float_as_uint(sB[(kc + lk) * 72 + n0 + lg]);
                    b[nt][1] = __float_as_uint(sB[(kc + 4 + lk) * 72 + n0 + lg]);
                }
#pragma unroll
                for (int mt = 0; mt < 2; mt++)
#pragma unroll
                    for (int nt = 0; nt < 2; nt++) {
                        asm volatile(
                            "mma.sync.aligned.m16n8k8.row.col.f32.tf32.tf32.f32 "
                            "{%0,%1,%2,%3}, {%4,%5,%6,%7}, {%8,%9}, {%0,%1,%2,%3};"
                            : "+f"(c[mt][nt][0]), "+f"(c[mt][nt][1]),
                              "+f"(c[mt][nt][2]), "+f"(c[mt][nt][3])
                            : "r"(a[mt][0]), "r"(a[mt][1]), "r"(a[mt][2]), "r"(a[mt][3]),
                              "r"(b[nt][0]), "r"(b[nt][1]));
                    }
            }
        }
    }

#pragma unroll
    for (int mt = 0; mt < 2; mt++) {
        int r0 = mt * 16 + lg;
        float b0 = cb[r0], b1 = cb[r0 + 8];
#pragma unroll
        for (int nt = 0; nt < 2; nt++) {
            int col = wid * 16 + nt * 8 + 2 * lk;
            float2 v0 = make_float2(c[mt][nt][0] + b0, c[mt][nt][1] + b0);
            float2 v1 = make_float2(c[mt][nt][2] + b1, c[mt][nt][3] + b1);
            *(float2*)&g_x[r0 * THW + p0 + col] = v0;
            *(float2*)&g_x[(r0 + 8) * THW + p0 + col] = v1;
        }
    }
}

// ---------------------------------------------------------------------------
// Stage 3: transformer — 560-base single-pass softmax, K/V pitch 36, and
// float4 (LDS.128 broadcast) K/V loads in the attention loop ONLY.
// Same bits, same summation order -> rel_err unchanged.
// ---------------------------------------------------------------------------
#define KV_PITCH 36

__device__ __forceinline__ float gelu_tanh(float a) {
    float inner = 0.7978845608028654f * fmaf(0.044715f * a, a * a, a);
    return 0.5f * a * (1.0f + tanhf(inner));
}

__global__ __launch_bounds__(128) void xf_kernel(
    const float* __restrict__ vid, float* __restrict__ out,
    const float* __restrict__ ln1_g, const float* __restrict__ ln1_b,
    const float* __restrict__ qkv_w, const float* __restrict__ qkv_b,
    const float* __restrict__ proj_w, const float* __restrict__ proj_b,
    const float* __restrict__ ln2_g, const float* __restrict__ ln2_b,
    const float* __restrict__ fc1_w, const float* __restrict__ fc1_b,
    const float* __restrict__ fc2_w, const float* __restrict__ fc2_b)
{
    extern __shared__ float sm[];
    float* s_qkvw = sm;                  // 3072
    float* s_qkvb = s_qkvw + 3072;       // 96
    float* s_projw = s_qkvb + 96;        // 1024
    float* s_projb = s_projw + 1024;     // 32
    float* s_fc1w = s_projb + 32;        // 2048
    float* s_fc1b = s_fc1w + 2048;       // 64
    float* s_fc2w = s_fc1b + 64;         // 2048
    float* s_fc2b = s_fc2w + 2048;       // 32
    float* s_g1 = s_fc2b + 32;           // 32
    float* s_b1 = s_g1 + 32;             // 32
    float* s_g2 = s_b1 + 32;             // 32
    float* s_b2 = s_g2 + 32;             // 32
    float* s_kv = s_b2 + 32;             // 2 windows x (2 x 64 x KV_PITCH); 16B-aligned base

    int tid = threadIdx.x;
    int wi = tid >> 6;
    int j = tid & 63;

    float* kbuf = s_kv + wi * (2 * 64 * KV_PITCH);
    float* vbuf = kbuf + 64 * KV_PITCH;

    int wg = blockIdx.x * 2 + wi;
    int t = wg >> 8, nh = (wg >> 4) & 15, nw = wg & 15;
    int h = nh * 8 + (j >> 3);
    int w = nw * 8 + (j & 7);
    int p = t * 16384 + h * 128 + w;

    float xr[32];
#pragma unroll
    for (int c = 0; c < 32; c++) xr[c] = g_x[c * THW + p];

    for (int L = 0; L < 2; L++) {
        __syncthreads();
        for (int idx = tid; idx < 3072; idx += 128) s_qkvw[idx] = qkv_w[L * 3072 + idx];
        for (int idx = tid; idx < 2048; idx += 128) {
            s_fc1w[idx] = fc1_w[L * 2048 + idx];
            s_fc2w[idx] = fc2_w[L * 2048 + idx];
        }
        for (int idx = tid; idx < 1024; idx += 128) s_projw[idx] = proj_w[L * 1024 + idx];
        if (tid < 96) s_qkvb[tid] = qkv_b[L * 96 + tid];
        if (tid < 64) s_fc1b[tid] = fc1_b[L * 64 + tid];
        if (tid < 32) {
            s_projb[tid] = proj_b[L * 32 + tid];
            s_fc2b[tid] = fc2_b[L * 32 + tid];
            s_g1[tid] = ln1_g[L * 32 + tid];
            s_b1[tid] = ln1_b[L * 32 + tid];
            s_g2[tid] = ln2_g[L * 32 + tid];
            s_b2[tid] = ln2_b[L * 32 + tid];
        }
        __syncthreads();

        float mu = 0.0f;
#pragma unroll
        for (int c = 0; c < 32; c++) mu += xr[c];
        mu *= 0.03125f;
        float var = 0.0f;
#pragma unroll
        for (int c = 0; c < 32; c++) { float d = xr[c] - mu; var = fmaf(d, d, var); }
        var *= 0.03125f;
        float rstd = rsqrtf(var + 1e-5f);
        float hv[32];
#pragma unroll
        for (int c = 0; c < 32; c++) hv[c] = (xr[c] - mu) * rstd * s_g1[c] + s_b1[c];

        float q[32];
#pragma unroll
        for (int jq = 0; jq < 32; jq++) {
            float s = s_qkvb[jq];
#pragma unroll
            for (int c = 0; c < 32; c++) s = fmaf(hv[c], s_qkvw[c * 96 + jq], s);
            q[jq] = s;
        }
        for (int jk = 0; jk < 32; jk++) {
            float s = s_qkvb[32 + jk];
#pragma unroll
            for (int c = 0; c < 32; c++) s = fmaf(hv[c], s_qkvw[c * 96 + 32 + jk], s);
            kbuf[j * KV_PITCH + jk] = s;
        }
        for (int jv = 0; jv < 32; jv++) {
            float s = s_qkvb[64 + jv];
#pragma unroll
            for (int c = 0; c < 32; c++) s = fmaf(hv[c], s_qkvw[c * 96 + 64 + jv], s);
            vbuf[j * KV_PITCH + jv] = s;
        }
        __syncthreads();

        // ---- attention: single pass, unnormalized softmax, float4 K/V ----
        float ov[32];
        const float scale = 0.3535533905932738f;
#pragma unroll
        for (int hh = 0; hh < 4; hh++) {
            const int base = hh * 8;
            float sum = 0.0f;
            float o0 = 0, o1 = 0, o2 = 0, o3 = 0, o4 = 0, o5 = 0, o6 = 0, o7 = 0;
            for (int kk = 0; kk < 64; kk++) {
                const float4 k0 = *(const float4*)&kbuf[kk * KV_PITCH + base];
                const float4 k1 = *(const float4*)&kbuf[kk * KV_PITCH + base + 4];
                float s = q[base] * k0.x;
                s = fmaf(q[base + 1], k0.y, s);
                s = fmaf(q[base + 2], k0.z, s);
                s = fmaf(q[base + 3], k0.w, s);
                s = fmaf(q[base + 4], k1.x, s);
                s = fmaf(q[base + 5], k1.y, s);
                s = fmaf(q[base + 6], k1.z, s);
                s = fmaf(q[base + 7], k1.w, s);
                float e = __expf(s * scale);
                sum += e;
                const float4 v0 = *(const float4*)&vbuf[kk * KV_PITCH + base];
                const float4 v1 = *(const float4*)&vbuf[kk * KV_PITCH + base + 4];
                o0 = fmaf(e, v0.x, o0); o1 = fmaf(e, v0.y, o1);
                o2 = fmaf(e, v0.z, o2); o3 = fmaf(e, v0.w, o3);
                o4 = fmaf(e, v1.x, o4); o5 = fmaf(e, v1.y, o5);
                o6 = fmaf(e, v1.z, o6); o7 = fmaf(e, v1.w, o7);
            }
            float inv = 1.0f / sum;
            ov[base + 0] = o0 * inv; ov[base + 1] = o1 * inv;
            ov[base + 2] = o2 * inv; ov[base + 3] = o3 * inv;
            ov[base + 4] = o4 * inv; ov[base + 5] = o5 * inv;
            ov[base + 6] = o6 * inv; ov[base + 7] = o7 * inv;
        }

#pragma unroll
        for (int c = 0; c < 32; c++) {
            float s = s_projb[c];
#pragma unroll
            for (int u = 0; u < 32; u++) s = fmaf(ov[u], s_projw[u * 32 + c], s);
            xr[c] += s;
        }

        mu = 0.0f;
#pragma unroll
        for (int c = 0; c < 32; c++) mu += xr[c];
        mu *= 0.03125f;
        var = 0.0f;
#pragma unroll
        for (int c = 0; c < 32; c++) { float d = xr[c] - mu; var = fmaf(d, d, var); }
        var *= 0.03125f;
        rstd = rsqrtf(var + 1e-5f);
#pragma unroll
        for (int c = 0; c < 32; c++) hv[c] = (xr[c] - mu) * rstd * s_g2[c] + s_b2[c];

        float acc[32];
#pragma unroll
        for (int c = 0; c < 32; c++) acc[c] = 0.0f;
        for (int u = 0; u < 64; u++) {
            float a = s_fc1b[u];
#pragma unroll
            for (int c = 0; c < 32; c++) a = fmaf(hv[c], s_fc1w[c * 64 + u], a);
            float g = gelu_tanh(a);
#pragma unroll
            for (int c = 0; c < 32; c++) acc[c] = fmaf(g, s_fc2w[u * 32 + c], acc[c]);
        }
#pragma unroll
        for (int c = 0; c < 32; c++) xr[c] += acc[c] + s_fc2b[c];
    }

#pragma unroll
    for (int c = 0; c < 32; c++) out[c * THW + p] = vid[c * THW + p] + xr[c];
}

// ---------------------------------------------------------------------------
extern "C" void kernel_launch(void* const* d_in, const int* in_sizes, int n_in,
                              void* d_out, int out_size) {
    const float* vid    = (const float*)d_in[0];
    const float* conv_w = (const float*)d_in[1];
    const float* conv_b = (const float*)d_in[2];
    const float* ln1_g  = (const float*)d_in[3];
    const float* ln1_b  = (const float*)d_in[4];
    const float* qkv_w  = (const float*)d_in[5];
    const float* qkv_b  = (const float*)d_in[6];
    const float* proj_w = (const float*)d_in[7];
    const float* proj_b = (const float*)d_in[8];
    const float* ln2_g  = (const float*)d_in[9];
    const float* ln2_b  = (const float*)d_in[10];
    const float* fc1_w  = (const float*)d_in[11];
    const float* fc1_b  = (const float*)d_in[12];
    const float* fc2_w  = (const float*)d_in[13];
    const float* fc2_b  = (const float*)d_in[14];
    float* out = (float*)d_out;

    nl_stack_kernel<<<1024, 128>>>(vid);      // 2 threads per voxel (560-base)
    wT_kernel<<<576, 128>>>(conv_w);
    conv_mma_kernel<<<1024, 128>>>(conv_b);   // 560-base simple conv (reverted)

    const int smem_bytes = (8544 + 2 * 2 * 64 * KV_PITCH) * (int)sizeof(float);  // 71040
    cudaFuncSetAttribute(xf_kernel, cudaFuncAttributeMaxDynamicSharedMemorySize, smem_bytes);
    xf_kernel<<<512, 128, smem_bytes>>>(vid, out,
                                        ln1_g, ln1_b, qkv_w, qkv_b, proj_w, proj_b,
                                        ln2_g, ln2_b, fc1_w, fc1_b, fc2_w, fc2_b);
}